// round 16
// baseline (speedup 1.0000x reference)
#include <cuda_runtime.h>
#include <cuda_fp16.h>
#include <cstdint>

#define MTOK 16384
#define FDIM 4096
#define CDIM 1024
#define NQ 8

#define BM 128
#define BN 128
#define BK 64
#define STAGES 3
#define KTILES (FDIM / BK)               // 64
#define SROWH 72                         // halves per smem row (144B: conflict-free LDSM phases)
#define A_HALVES (BM * SROWH)            // 9216
#define STAGE_BYTES (2 * A_HALVES * 2)   // 36864 (A then B)
#define SMEM_TOTAL (STAGES * STAGE_BYTES)        // 110592 -> 2 CTAs/SM

// ---- scratch (device globals; allocation is forbidden) ----
__device__ __align__(128) __half g_h[(size_t)MTOK * FDIM];        // 128 MB
__device__ __align__(128) __half g_w2h[(size_t)CDIM * FDIM];      // 8 MB

__device__ __forceinline__ uint32_t smem_u32(const void* p) {
    uint32_t a;
    asm("{ .reg .u64 t; cvta.to.shared.u64 t, %1; cvt.u32.u64 %0, t; }" : "=r"(a) : "l"(p));
    return a;
}

__device__ __forceinline__ void cp_async16(uint32_t dst, const void* src) {
    asm volatile("cp.async.cg.shared.global [%0], [%1], 16;" :: "r"(dst), "l"(src));
}
#define CP_COMMIT() asm volatile("cp.async.commit_group;" ::: "memory")
#define CP_WAIT1()  asm volatile("cp.async.wait_group 1;" ::: "memory")

// fp16 MMA, fp32 accumulator: same 10-bit mantissa as tf32, 2x MAC/instr.
__device__ __forceinline__ void mma_f16(float* c, const uint32_t* a, uint32_t b0, uint32_t b1) {
    asm volatile(
        "mma.sync.aligned.m16n8k16.row.col.f32.f16.f16.f32 "
        "{%0,%1,%2,%3}, {%4,%5,%6,%7}, {%8,%9}, {%0,%1,%2,%3};"
        : "+f"(c[0]), "+f"(c[1]), "+f"(c[2]), "+f"(c[3])
        : "r"(a[0]), "r"(a[1]), "r"(a[2]), "r"(a[3]), "r"(b0), "r"(b1));
}

__device__ __forceinline__ void ldsm4(uint32_t* r, uint32_t addr) {
    asm volatile("ldmatrix.sync.aligned.m8n8.x4.shared.b16 {%0,%1,%2,%3}, [%4];"
                 : "=r"(r[0]), "=r"(r[1]), "=r"(r[2]), "=r"(r[3]) : "r"(addr));
}

// ==================== pass 0: w2 -> fp16 ====================
__global__ void __launch_bounds__(256) w2h_kernel(const float* __restrict__ w2) {
    size_t i = (size_t)(blockIdx.x * 256 + threadIdx.x) * 4;
    float4 v = *(const float4*)(w2 + i);
    __half2* dst = (__half2*)(g_w2h + i);
    dst[0] = __floats2half2_rn(v.x, v.y);
    dst[1] = __floats2half2_rn(v.z, v.w);
}

// ==================== pass 1: h = relu(cumprod(cos(x[:,:8])) @ w1^T + b1) -> fp16 ====
// q computed inline (fused): each thread builds the cumprod for 2 tokens into smem.
__global__ void __launch_bounds__(256) h_kernel(const float* __restrict__ x,
                                                const float* __restrict__ w1,
                                                const float* __restrict__ b1) {
    __shared__ float qs[512 * NQ];  // 16 KB
    int t = threadIdx.x;

#pragma unroll
    for (int j = 0; j < 2; j++) {
        int tokl = t * 2 + j;
        const float4* xp = (const float4*)(x + ((size_t)blockIdx.y * 512 + tokl) * CDIM);
        float4 a = xp[0], b = xp[1];
        float* qr = qs + tokl * NQ;
        float q0 = cosf(a.x);      qr[0] = q0;
        float q1 = q0 * cosf(a.y); qr[1] = q1;
        float q2 = q1 * cosf(a.z); qr[2] = q2;
        float q3 = q2 * cosf(a.w); qr[3] = q3;
        float q4 = q3 * cosf(b.x); qr[4] = q4;
        float q5 = q4 * cosf(b.y); qr[5] = q5;
        float q6 = q5 * cosf(b.z); qr[6] = q6;
        float q7 = q6 * cosf(b.w); qr[7] = q7;
    }
    __syncthreads();

    int f0 = blockIdx.x * 64 + (t & 31) * 2;
    int tok0 = (t >> 5) * 64;
    float4 wa0 = __ldg((const float4*)(w1 + (size_t)f0 * NQ));
    float4 wb0 = __ldg((const float4*)(w1 + (size_t)f0 * NQ + 4));
    float4 wa1 = __ldg((const float4*)(w1 + (size_t)(f0 + 1) * NQ));
    float4 wb1 = __ldg((const float4*)(w1 + (size_t)(f0 + 1) * NQ + 4));
    float bi0 = __ldg(b1 + f0), bi1 = __ldg(b1 + f0 + 1);
    __half* hp = g_h + ((size_t)(blockIdx.y * 512 + tok0)) * FDIM + f0;

#pragma unroll 4
    for (int i = 0; i < 64; i++) {
        const float4* qr = (const float4*)(qs + (tok0 + i) * NQ);
        float4 qa = qr[0], qb = qr[1];
        float v0 = bi0, v1 = bi1;
        v0 = fmaf(qa.x, wa0.x, v0); v1 = fmaf(qa.x, wa1.x, v1);
        v0 = fmaf(qa.y, wa0.y, v0); v1 = fmaf(qa.y, wa1.y, v1);
        v0 = fmaf(qa.z, wa0.z, v0); v1 = fmaf(qa.z, wa1.z, v1);
        v0 = fmaf(qa.w, wa0.w, v0); v1 = fmaf(qa.w, wa1.w, v1);
        v0 = fmaf(qb.x, wb0.x, v0); v1 = fmaf(qb.x, wb1.x, v1);
        v0 = fmaf(qb.y, wb0.y, v0); v1 = fmaf(qb.y, wb1.y, v1);
        v0 = fmaf(qb.z, wb0.z, v0); v1 = fmaf(qb.z, wb1.z, v1);
        v0 = fmaf(qb.w, wb0.w, v0); v1 = fmaf(qb.w, wb1.w, v1);
        *(__half2*)(hp + (size_t)i * FDIM) = __floats2half2_rn(fmaxf(v0, 0.0f), fmaxf(v1, 0.0f));
    }
}

// ==================== pass 2: out = h @ w2^T + b2 (mma.sync fp16, fp32 acc) ====
// CTA 128x128x64(fp16), 4 warps (2x2), warp tile 64x64; 3 stages, 2 CTAs/SM.
// ONE barrier per ktile: wait_group(1) -> barrier -> issue load(t+2) (safe: all
// warps are past iter t-1, so overwriting stage (t-1)%3 cannot race a reader).
__device__ __forceinline__ void load_tile(uint32_t stage_b, int m0, int n0, int k0, int tid) {
#pragma unroll
    for (int i = 0; i < 8; i++) {
        int idx = tid + i * 128;
        int row = idx >> 3, c16 = idx & 7;
        cp_async16(stage_b + row * (SROWH * 2) + c16 * 16,
                   (const char*)(g_h + (size_t)(m0 + row) * FDIM + k0) + c16 * 16);
    }
#pragma unroll
    for (int i = 0; i < 8; i++) {
        int idx = tid + i * 128;
        int row = idx >> 3, c16 = idx & 7;
        cp_async16(stage_b + A_HALVES * 2 + row * (SROWH * 2) + c16 * 16,
                   (const char*)(g_w2h + (size_t)(n0 + row) * FDIM + k0) + c16 * 16);
    }
}

__global__ void __launch_bounds__(128, 2) gemm2_kernel(const float* __restrict__ b2,
                                                       float* __restrict__ out) {
    extern __shared__ __align__(16) uint32_t sm[];
    uint32_t sb = smem_u32(sm);
    int tid = threadIdx.x, wid = tid >> 5, lane = tid & 31;
    int wm = wid & 1, wn = wid >> 1;          // warp grid 2 x 2; warp tile 64 x 64
    int g = lane >> 2, t4 = lane & 3;
    int m0 = blockIdx.y * BM, n0 = blockIdx.x * BN;

    float acc[4][8][4];
#pragma unroll
    for (int mt = 0; mt < 4; mt++)
#pragma unroll
        for (int nt = 0; nt < 8; nt++)
#pragma unroll
            for (int r = 0; r < 4; r++) acc[mt][nt][r] = 0.0f;

    // prologue: tiles 0,1 into stages 0,1
    load_tile(sb, m0, n0, 0, tid);                   CP_COMMIT();
    load_tile(sb + STAGE_BYTES, m0, n0, BK, tid);    CP_COMMIT();

    // A ldmatrix.x4: tiles (m0-7,k0) (m8-15,k0) (m0-7,k8) (m8-15,k8) -> frag a0..a3.
    const uint32_t aOff =
        ((uint32_t)(wm * 64 + (lane & 15)) * SROWH + ((lane >> 4) * 8)) * 2;
    // B ldmatrix.x4: r0,r1 = b0,b1 of n-tile 2p; r2,r3 = b0,b1 of n-tile 2p+1.
    const uint32_t bOff = (uint32_t)(A_HALVES +
        ((wn * 64 + (lane & 7) + ((lane >> 4) << 3)) * SROWH + (((lane >> 3) & 1) * 8))) * 2;

    int s = 0, sw = 2;   // read stage, write stage (incremental mod-3)
    for (int t = 0; t < KTILES; t++) {
        CP_WAIT1();              // tile t resident (this thread's groups; <=1 pending after)
        __syncthreads();         // all loads visible; all warps past iter t-1 reads
        if (t + 2 < KTILES)
            load_tile(sb + sw * STAGE_BYTES, m0, n0, (t + 2) * BK, tid);
        CP_COMMIT();             // uniform group accounting (empty at tail)

        uint32_t stg = sb + s * STAGE_BYTES;
#pragma unroll
        for (int ks = 0; ks < 4; ks++) {       // 4 x k16
            uint32_t a[4][4], b[4][4];
#pragma unroll
            for (int mt = 0; mt < 4; mt++)
                ldsm4(a[mt], stg + aOff + (uint32_t)(mt * 16 * SROWH + ks * 16) * 2);
#pragma unroll
            for (int p = 0; p < 4; p++)
                ldsm4(b[p], stg + bOff + (uint32_t)(p * 16 * SROWH + ks * 16) * 2);
#pragma unroll
            for (int mt = 0; mt < 4; mt++)
#pragma unroll
                for (int p = 0; p < 4; p++) {
                    mma_f16(acc[mt][2 * p],     a[mt], b[p][0], b[p][1]);
                    mma_f16(acc[mt][2 * p + 1], a[mt], b[p][2], b[p][3]);
                }
        }
        s = (s == 2) ? 0 : s + 1;
        sw = (sw == 2) ? 0 : sw + 1;
    }

    // epilogue: c0/c1 at (row g, cols 2t4..+1), c2/c3 at row g+8
#pragma unroll
    for (int mt = 0; mt < 4; mt++) {
        int mrow = m0 + wm * 64 + mt * 16 + g;
#pragma unroll
        for (int nt = 0; nt < 8; nt++) {
            int nc = n0 + wn * 64 + nt * 8 + 2 * t4;
            float bx = __ldg(b2 + nc), by = __ldg(b2 + nc + 1);
            float2 v0 = make_float2(acc[mt][nt][0] + bx, acc[mt][nt][1] + by);
            float2 v1 = make_float2(acc[mt][nt][2] + bx, acc[mt][nt][3] + by);
            *(float2*)(out + (size_t)mrow * CDIM + nc) = v0;
            *(float2*)(out + (size_t)(mrow + 8) * CDIM + nc) = v1;
        }
    }
}

// ==================== launch ====================
extern "C" void kernel_launch(void* const* d_in, const int* in_sizes, int n_in,
                              void* d_out, int out_size) {
    const float* x  = (const float*)d_in[0];
    // d_in[1] = circuit_params: provably cancels out of the measured expectations
    const float* w1 = (const float*)d_in[2];
    const float* b1 = (const float*)d_in[3];
    const float* w2 = (const float*)d_in[4];
    const float* b2 = (const float*)d_in[5];
    float* out = (float*)d_out;

    w2h_kernel<<<(CDIM * FDIM) / (256 * 4), 256>>>(w2);
    h_kernel<<<dim3(FDIM / 64, MTOK / 512), 256>>>(x, w1, b1);

    cudaFuncSetAttribute(gemm2_kernel, cudaFuncAttributeMaxDynamicSharedMemorySize, SMEM_TOTAL);
    gemm2_kernel<<<dim3(CDIM / BN, MTOK / BM), 128, SMEM_TOTAL>>>(b2, out);
}

// round 17
// speedup vs baseline: 1.0285x; 1.0285x over previous
#include <cuda_runtime.h>
#include <cuda_fp16.h>
#include <cstdint>

#define MTOK 16384
#define FDIM 4096
#define CDIM 1024
#define NQ 8

#define BM 128
#define BN 128
#define BK 64
#define STAGES 3
#define KTILES (FDIM / BK)               // 64
#define SROWH 72                         // halves per smem row (144B: conflict-free LDSM phases)
#define A_HALVES (BM * SROWH)            // 9216
#define STAGE_BYTES (2 * A_HALVES * 2)   // 36864 (A then B)
#define SMEM_TOTAL (STAGES * STAGE_BYTES)        // 110592 -> 2 CTAs/SM

// ---- scratch (device globals; allocation is forbidden) ----
__device__ __align__(128) __half g_h[(size_t)MTOK * FDIM];        // 128 MB
__device__ __align__(128) __half g_w2h[(size_t)CDIM * FDIM];      // 8 MB

__device__ __forceinline__ uint32_t smem_u32(const void* p) {
    uint32_t a;
    asm("{ .reg .u64 t; cvta.to.shared.u64 t, %1; cvt.u32.u64 %0, t; }" : "=r"(a) : "l"(p));
    return a;
}

__device__ __forceinline__ void cp_async16(uint32_t dst, const void* src) {
    asm volatile("cp.async.cg.shared.global [%0], [%1], 16;" :: "r"(dst), "l"(src));
}
#define CP_COMMIT() asm volatile("cp.async.commit_group;" ::: "memory")
#define CP_WAIT2()  asm volatile("cp.async.wait_group 2;" ::: "memory")

// fp16 MMA, fp32 accumulator: same 10-bit mantissa as tf32, 2x MAC/instr.
__device__ __forceinline__ void mma_f16(float* c, const uint32_t* a, uint32_t b0, uint32_t b1) {
    asm volatile(
        "mma.sync.aligned.m16n8k16.row.col.f32.f16.f16.f32 "
        "{%0,%1,%2,%3}, {%4,%5,%6,%7}, {%8,%9}, {%0,%1,%2,%3};"
        : "+f"(c[0]), "+f"(c[1]), "+f"(c[2]), "+f"(c[3])
        : "r"(a[0]), "r"(a[1]), "r"(a[2]), "r"(a[3]), "r"(b0), "r"(b1));
}

__device__ __forceinline__ void ldsm4(uint32_t* r, uint32_t addr) {
    asm volatile("ldmatrix.sync.aligned.m8n8.x4.shared.b16 {%0,%1,%2,%3}, [%4];"
                 : "=r"(r[0]), "=r"(r[1]), "=r"(r[2]), "=r"(r[3]) : "r"(addr));
}

// ==================== pass 0: w2 -> fp16 ====================
__global__ void __launch_bounds__(256) w2h_kernel(const float* __restrict__ w2) {
    size_t i = (size_t)(blockIdx.x * 256 + threadIdx.x) * 4;
    float4 v = *(const float4*)(w2 + i);
    __half2* dst = (__half2*)(g_w2h + i);
    dst[0] = __floats2half2_rn(v.x, v.y);
    dst[1] = __floats2half2_rn(v.z, v.w);
}

// ==================== pass 1: h = relu(cumprod(cos(x[:,:8])) @ w1^T + b1) -> fp16 ====
__global__ void __launch_bounds__(256) h_kernel(const float* __restrict__ x,
                                                const float* __restrict__ w1,
                                                const float* __restrict__ b1) {
    __shared__ float qs[512 * NQ];  // 16 KB
    int t = threadIdx.x;

#pragma unroll
    for (int j = 0; j < 2; j++) {
        int tokl = t * 2 + j;
        const float4* xp = (const float4*)(x + ((size_t)blockIdx.y * 512 + tokl) * CDIM);
        float4 a = xp[0], b = xp[1];
        float* qr = qs + tokl * NQ;
        float q0 = cosf(a.x);      qr[0] = q0;
        float q1 = q0 * cosf(a.y); qr[1] = q1;
        float q2 = q1 * cosf(a.z); qr[2] = q2;
        float q3 = q2 * cosf(a.w); qr[3] = q3;
        float q4 = q3 * cosf(b.x); qr[4] = q4;
        float q5 = q4 * cosf(b.y); qr[5] = q5;
        float q6 = q5 * cosf(b.z); qr[6] = q6;
        float q7 = q6 * cosf(b.w); qr[7] = q7;
    }
    __syncthreads();

    int f0 = blockIdx.x * 64 + (t & 31) * 2;
    int tok0 = (t >> 5) * 64;
    float4 wa0 = __ldg((const float4*)(w1 + (size_t)f0 * NQ));
    float4 wb0 = __ldg((const float4*)(w1 + (size_t)f0 * NQ + 4));
    float4 wa1 = __ldg((const float4*)(w1 + (size_t)(f0 + 1) * NQ));
    float4 wb1 = __ldg((const float4*)(w1 + (size_t)(f0 + 1) * NQ + 4));
    float bi0 = __ldg(b1 + f0), bi1 = __ldg(b1 + f0 + 1);
    __half* hp = g_h + ((size_t)(blockIdx.y * 512 + tok0)) * FDIM + f0;

#pragma unroll 4
    for (int i = 0; i < 64; i++) {
        const float4* qr = (const float4*)(qs + (tok0 + i) * NQ);
        float4 qa = qr[0], qb = qr[1];
        float v0 = bi0, v1 = bi1;
        v0 = fmaf(qa.x, wa0.x, v0); v1 = fmaf(qa.x, wa1.x, v1);
        v0 = fmaf(qa.y, wa0.y, v0); v1 = fmaf(qa.y, wa1.y, v1);
        v0 = fmaf(qa.z, wa0.z, v0); v1 = fmaf(qa.z, wa1.z, v1);
        v0 = fmaf(qa.w, wa0.w, v0); v1 = fmaf(qa.w, wa1.w, v1);
        v0 = fmaf(qb.x, wb0.x, v0); v1 = fmaf(qb.x, wb1.x, v1);
        v0 = fmaf(qb.y, wb0.y, v0); v1 = fmaf(qb.y, wb1.y, v1);
        v0 = fmaf(qb.z, wb0.z, v0); v1 = fmaf(qb.z, wb1.z, v1);
        v0 = fmaf(qb.w, wb0.w, v0); v1 = fmaf(qb.w, wb1.w, v1);
        *(__half2*)(hp + (size_t)i * FDIM) = __floats2half2_rn(fmaxf(v0, 0.0f), fmaxf(v1, 0.0f));
    }
}

// ==================== pass 2: out = h @ w2^T + b2 (mma.sync fp16, fp32 acc) ====
// CTA 128x128x64(fp16) with EIGHT warps (2m x 4n), warp tile 64x32; 3 stages,
// 2 CTAs/SM -> 16 warps/SM, 4/SMSP for latency hiding. R15 loop structure
// (load-first, two barriers) restored — R16's reorder regressed.
__device__ __forceinline__ void load_tile(uint32_t stage_b, int m0, int n0, int k0, int tid) {
#pragma unroll
    for (int i = 0; i < 4; i++) {
        int idx = tid + i * 256;
        int row = idx >> 3, c16 = idx & 7;
        cp_async16(stage_b + row * (SROWH * 2) + c16 * 16,
                   (const char*)(g_h + (size_t)(m0 + row) * FDIM + k0) + c16 * 16);
    }
#pragma unroll
    for (int i = 0; i < 4; i++) {
        int idx = tid + i * 256;
        int row = idx >> 3, c16 = idx & 7;
        cp_async16(stage_b + A_HALVES * 2 + row * (SROWH * 2) + c16 * 16,
                   (const char*)(g_w2h + (size_t)(n0 + row) * FDIM + k0) + c16 * 16);
    }
}

__global__ void __launch_bounds__(256, 2) gemm2_kernel(const float* __restrict__ b2,
                                                       float* __restrict__ out) {
    extern __shared__ __align__(16) uint32_t sm[];
    uint32_t sb = smem_u32(sm);
    int tid = threadIdx.x, wid = tid >> 5, lane = tid & 31;
    int wm = wid & 1, wn = wid >> 1;          // warp grid 2(m) x 4(n); warp tile 64 x 32
    int g = lane >> 2, t4 = lane & 3;
    int m0 = blockIdx.y * BM, n0 = blockIdx.x * BN;

    float acc[4][4][4];
#pragma unroll
    for (int mt = 0; mt < 4; mt++)
#pragma unroll
        for (int nt = 0; nt < 4; nt++)
#pragma unroll
            for (int r = 0; r < 4; r++) acc[mt][nt][r] = 0.0f;

    // prologue: tiles 0,1 into stages 0,1
    load_tile(sb, m0, n0, 0, tid);                   CP_COMMIT();
    load_tile(sb + STAGE_BYTES, m0, n0, BK, tid);    CP_COMMIT();

    // A ldmatrix.x4: tiles (m0-7,k0) (m8-15,k0) (m0-7,k8) (m8-15,k8) -> frag a0..a3.
    const uint32_t aOff =
        ((uint32_t)(wm * 64 + (lane & 15)) * SROWH + ((lane >> 4) * 8)) * 2;
    // B ldmatrix.x4: r0,r1 = b0,b1 of n-tile 2p; r2,r3 = b0,b1 of n-tile 2p+1.
    const uint32_t bOff = (uint32_t)(A_HALVES +
        ((wn * 32 + (lane & 7) + ((lane >> 4) << 3)) * SROWH + (((lane >> 3) & 1) * 8))) * 2;

    int s = 0, sw = 2;   // read stage, write stage (incremental mod-3)
    for (int t = 0; t < KTILES; t++) {
        if (t + 2 < KTILES)
            load_tile(sb + sw * STAGE_BYTES, m0, n0, (t + 2) * BK, tid);
        CP_COMMIT();             // uniform group accounting (empty at tail)
        CP_WAIT2();              // tile t resident (this thread's groups)
        __syncthreads();         // everyone's loads visible

        uint32_t stg = sb + s * STAGE_BYTES;
#pragma unroll
        for (int ks = 0; ks < 4; ks++) {       // 4 x k16
            uint32_t a[4][4], b[2][4];
#pragma unroll
            for (int mt = 0; mt < 4; mt++)
                ldsm4(a[mt], stg + aOff + (uint32_t)(mt * 16 * SROWH + ks * 16) * 2);
#pragma unroll
            for (int p = 0; p < 2; p++)
                ldsm4(b[p], stg + bOff + (uint32_t)(p * 16 * SROWH + ks * 16) * 2);
#pragma unroll
            for (int mt = 0; mt < 4; mt++)
#pragma unroll
                for (int p = 0; p < 2; p++) {
                    mma_f16(acc[mt][2 * p],     a[mt], b[p][0], b[p][1]);
                    mma_f16(acc[mt][2 * p + 1], a[mt], b[p][2], b[p][3]);
                }
        }
        __syncthreads();         // stage s reads done -> reusable as write target
        s = (s == 2) ? 0 : s + 1;
        sw = (sw == 2) ? 0 : sw + 1;
    }

    // epilogue: c0/c1 at (row g, cols 2t4..+1), c2/c3 at row g+8
#pragma unroll
    for (int mt = 0; mt < 4; mt++) {
        int mrow = m0 + wm * 64 + mt * 16 + g;
#pragma unroll
        for (int nt = 0; nt < 4; nt++) {
            int nc = n0 + wn * 32 + nt * 8 + 2 * t4;
            float bx = __ldg(b2 + nc), by = __ldg(b2 + nc + 1);
            float2 v0 = make_float2(acc[mt][nt][0] + bx, acc[mt][nt][1] + by);
            float2 v1 = make_float2(acc[mt][nt][2] + bx, acc[mt][nt][3] + by);
            *(float2*)(out + (size_t)mrow * CDIM + nc) = v0;
            *(float2*)(out + (size_t)(mrow + 8) * CDIM + nc) = v1;
        }
    }
}

// ==================== launch ====================
extern "C" void kernel_launch(void* const* d_in, const int* in_sizes, int n_in,
                              void* d_out, int out_size) {
    const float* x  = (const float*)d_in[0];
    // d_in[1] = circuit_params: provably cancels out of the measured expectations
    const float* w1 = (const float*)d_in[2];
    const float* b1 = (const float*)d_in[3];
    const float* w2 = (const float*)d_in[4];
    const float* b2 = (const float*)d_in[5];
    float* out = (float*)d_out;

    w2h_kernel<<<(CDIM * FDIM) / (256 * 4), 256>>>(w2);
    h_kernel<<<dim3(FDIM / 64, MTOK / 512), 256>>>(x, w1, b1);

    cudaFuncSetAttribute(gemm2_kernel, cudaFuncAttributeMaxDynamicSharedMemorySize, SMEM_TOTAL);
    gemm2_kernel<<<dim3(CDIM / BN, MTOK / BM), 256, SMEM_TOTAL>>>(b2, out);
}